// round 12
// baseline (speedup 1.0000x reference)
#include <cuda_runtime.h>
#include <math.h>

// Problem constants
#define B_   64
#define L_   512
#define D_   256
#define H_   256
#define T_   11
#define M_   (B_ * L_)      // 32768 rows (b*L + l)
#define G4H  (4 * H_)       // 1024 gate rows (i,f,g,o blocks of 256)

#define NBLK_LSTM 128       // persistent blocks (<=148 SMs, 1/SM)

// smem layout (floats)
#define OFF_W    0          // W_hh: 128 rows * 260   (reused as viterbi lg)
#define OFF_H    33280      // h: 8 * 260             (reused as viterbi bps)
#define OFF_G    35360      // G: 128 * 9
#define OFF_WS   36512      // producer W tiles: 2*16*132  (reused as Wout)
#define OFF_ES   40736      // producer E tiles: 2*16*132
#define OFF_CNT  44960      // produced-group counter
#define SMEM_FLOATS 44964

#define BAR_C() asm volatile("bar.sync 1, 256;" ::: "memory")
#define BAR_P() asm volatile("bar.sync 2, 256;" ::: "memory")

// ---------------------------------------------------------------------------
// Scratch (static __device__ — no allocations allowed)
// ---------------------------------------------------------------------------
__device__ float g_gates[2 * 32768 * 1024];     // [dir][b*L+l][4H] input-proj + bias
__device__ float g_hseq[32768 * 512];           // [b*L+l][512] = concat(hf, hb)
__device__ float g_hbuf[2][2][B_ * H_];         // [dir][parity][b*H + j]
__device__ float g_logits[32768 * T_];          // [b*L+l][T]
__device__ unsigned int g_cnt[2][8];            // per-(dir, batch-group) h-completion
__device__ unsigned int g_lcnt[8];              // per-batch-group logits completion

// ---------------------------------------------------------------------------
// Init: copy h0 into parity-0 h buffers, reset counters
// ---------------------------------------------------------------------------
__global__ void init_kernel(const float* __restrict__ h0) {
    int i = blockIdx.x * blockDim.x + threadIdx.x;
    if (i < 16) ((unsigned int*)g_cnt)[i] = 0u;
    if (i < 8) g_lcnt[i] = 0u;
    if (i < 2 * B_ * H_) {
        int dir = i / (B_ * H_);
        int rem = i - dir * (B_ * H_);
        g_hbuf[dir][0][rem] = h0[i];
    }
}

// ---------------------------------------------------------------------------
// Fused persistent kernel:
//   warps 0-7  : input-projection producer for THIS block's gate slice
//   warps 8-15 : recurrence; then logits slice; dir0 warp 8 then Viterbi
// ---------------------------------------------------------------------------
__global__ __launch_bounds__(512, 1) void lstm_kernel(
    const float* __restrict__ c0,
    const float* __restrict__ Whh_f, const float* __restrict__ Whh_b,
    const int* __restrict__ sent, const float* __restrict__ emb,
    const float* __restrict__ Wih_f, const float* __restrict__ b_f,
    const float* __restrict__ Wih_b, const float* __restrict__ b_b,
    const float* __restrict__ Wout, const float* __restrict__ bout,
    const float* __restrict__ trans, float* scores, float* paths)
{
    extern __shared__ float sm[];
    float4* Wsm4 = (float4*)(sm + OFF_W);          // 128 rows * 65 float4 (pad)
    float4* hsm4 = (float4*)(sm + OFF_H);          // 8 batches * 65 float4
    float*  Gsm  = sm + OFF_G;                     // 128 rows * 9 (pad)
    float*  Ws   = sm + OFF_WS;                    // [buf][k=16][n=128 pad 132]
    float*  Es   = sm + OFF_ES;                    // [buf][k=16][m=128 pad 132]
    volatile unsigned int* prod = (volatile unsigned int*)(sm + OFF_CNT);

    const int tid = threadIdx.x;
    const int bid = blockIdx.x;
    const int dir = bid >> 6;
    const int sub = bid & 63;
    const int bg  = sub >> 3;              // batch group 0..7
    const int b0  = bg * 8;                // batch tile base
    const int j0  = (sub & 7) * 32;        // hidden tile base

    if (tid == 0) *prod = 0u;

    // Compute threads preload W_hh slice: smem row r -> gate g=r>>5, j0+(r&31)
    if (tid >= 256) {
        const int ctid = tid - 256;
        const float4* Wg4 = (const float4*)(dir ? Whh_b : Whh_f);
        for (int idx = ctid; idx < 128 * 64; idx += 256) {
            int r = idx >> 6, k4 = idx & 63;
            int g = r >> 5, jj = r & 31;
            Wsm4[r * 65 + k4] = Wg4[(size_t)(g * H_ + j0 + jj) * 64 + k4];
        }
    }
    __syncthreads();   // everyone: prod init + W_hh visible

    if (tid < 256) {
        // ================= PRODUCER (warps 0-7, low priority) =============
        const float* Wih  = dir ? Wih_b : Wih_f;
        const float* bias = dir ? b_b  : b_f;
        float* outBase = g_gates + (size_t)dir * M_ * G4H;

        const int n   = tid & 127;          // stage row id (gate-row / m index)
        const int kq  = tid >> 7;           // 0/1: which 8-k half this thread stages
        const int nt  = tid >> 4;           // 0..15: n-tile (8 rows)
        const int mt  = tid & 15;           // 0..15: m-tile (8 cols)

        const int gblk = n >> 5, jj = n & 31;
        const float* wRow = Wih + (size_t)(gblk * H_ + j0 + jj) * D_ + kq * 8;

        const int growN0 = (nt >> 2) * H_ + j0 + (nt & 3) * 8;   // first of 8 n-rows
        float bias8[8];
#pragma unroll
        for (int j = 0; j < 8; j++) bias8[j] = bias[growN0 + j];

        for (int g = 0; g < 32; g++) {
            const int lbase = (dir ? (31 - g) : g) * 16;

            const int sv = sent[(b0 + (n & 7)) * L_ + lbase + (n >> 3)];
            const float* eRow = emb + (size_t)sv * D_ + kq * 8;

            // Preload chunk 0 into buf 0
            {
                float4 w0 = *(const float4*)(wRow);
                float4 w1 = *(const float4*)(wRow + 4);
                float4 e0 = *(const float4*)(eRow);
                float4 e1 = *(const float4*)(eRow + 4);
                float* Wd = Ws + (kq * 8) * 132 + n;
                Wd[0*132]=w0.x; Wd[1*132]=w0.y; Wd[2*132]=w0.z; Wd[3*132]=w0.w;
                Wd[4*132]=w1.x; Wd[5*132]=w1.y; Wd[6*132]=w1.z; Wd[7*132]=w1.w;
                float* Ed = Es + (kq * 8) * 132 + n;
                Ed[0*132]=e0.x; Ed[1*132]=e0.y; Ed[2*132]=e0.z; Ed[3*132]=e0.w;
                Ed[4*132]=e1.x; Ed[5*132]=e1.y; Ed[6*132]=e1.z; Ed[7*132]=e1.w;
            }
            BAR_P();

            float acc[8][8];
#pragma unroll
            for (int i = 0; i < 8; i++)
#pragma unroll
                for (int j = 0; j < 8; j++) acc[i][j] = 0.f;

            for (int c = 0; c < 16; c++) {
                float4 nw0, nw1, ne0, ne1;
                if (c < 15) {
                    nw0 = *(const float4*)(wRow + (c + 1) * 16);
                    nw1 = *(const float4*)(wRow + (c + 1) * 16 + 4);
                    ne0 = *(const float4*)(eRow + (c + 1) * 16);
                    ne1 = *(const float4*)(eRow + (c + 1) * 16 + 4);
                }
                const float* Wb = Ws + (c & 1) * 2112;
                const float* Eb = Es + (c & 1) * 2112;
#pragma unroll
                for (int k = 0; k < 16; k++) {
                    float4 a0 = *(const float4*)(Wb + k * 132 + nt * 8);
                    float4 a1 = *(const float4*)(Wb + k * 132 + nt * 8 + 4);
                    float4 bb0 = *(const float4*)(Eb + k * 132 + mt * 8);
                    float4 bb1 = *(const float4*)(Eb + k * 132 + mt * 8 + 4);
                    float wv[8] = {a0.x,a0.y,a0.z,a0.w,a1.x,a1.y,a1.z,a1.w};
                    float ev[8] = {bb0.x,bb0.y,bb0.z,bb0.w,bb1.x,bb1.y,bb1.z,bb1.w};
#pragma unroll
                    for (int i = 0; i < 8; i++)
#pragma unroll
                        for (int j = 0; j < 8; j++)
                            acc[i][j] = fmaf(wv[i], ev[j], acc[i][j]);
                }
                if (c < 15) {
                    float* Wd = Ws + ((c + 1) & 1) * 2112 + (kq * 8) * 132 + n;
                    Wd[0*132]=nw0.x; Wd[1*132]=nw0.y; Wd[2*132]=nw0.z; Wd[3*132]=nw0.w;
                    Wd[4*132]=nw1.x; Wd[5*132]=nw1.y; Wd[6*132]=nw1.z; Wd[7*132]=nw1.w;
                    float* Ed = Es + ((c + 1) & 1) * 2112 + (kq * 8) * 132 + n;
                    Ed[0*132]=ne0.x; Ed[1*132]=ne0.y; Ed[2*132]=ne0.z; Ed[3*132]=ne0.w;
                    Ed[4*132]=ne1.x; Ed[5*132]=ne1.y; Ed[6*132]=ne1.z; Ed[7*132]=ne1.w;
                }
                BAR_P();
            }

            // Write out 8 m columns (each 8 consecutive gate rows)
#pragma unroll
            for (int j = 0; j < 8; j++) {
                int m = mt * 8 + j;
                int bi = m & 7, li = m >> 3;
                float* dst = outBase +
                    ((size_t)(b0 + bi) * L_ + (lbase + li)) * G4H + growN0;
                float4 o0 = make_float4(acc[0][j] + bias8[0], acc[1][j] + bias8[1],
                                        acc[2][j] + bias8[2], acc[3][j] + bias8[3]);
                float4 o1 = make_float4(acc[4][j] + bias8[4], acc[5][j] + bias8[5],
                                        acc[6][j] + bias8[6], acc[7][j] + bias8[7]);
                __stcg((float4*)dst, o0);
                __stcg((float4*)(dst + 4), o1);
            }
            __threadfence();      // my gate stores visible before counter bump
            BAR_P();              // all producers done with this group
            if (tid == 0) *prod = (unsigned)(g + 1);
        }
        return;   // producers exit
    }

    // ================= COMPUTE (warps 8-15, high priority) ================
    const int ctid = tid - 256;

    // Cell-update thread mapping
    const int ub = ctid >> 5, ujj = ctid & 31;
    float c = c0[dir * B_ * H_ + (b0 + ub) * H_ + j0 + ujj];

    // GEMM thread mapping: 8-way interleaved k-split
    const int ks   = ctid & 7;
    const int tile = ctid >> 3;
    const int rt   = tile >> 1;            // 0..15 -> rows rt*8..rt*8+7
    const int bq   = tile & 1;             // batches bq*4..bq*4+3
    const int ri_fin = ((ks & 1) << 2) | (ks & 2) | ((ks >> 2) & 1);
    const int row_fin = rt * 8 + ri_fin;
    const int grow_fin = (row_fin >> 5) * H_ + j0 + (row_fin & 31);

    const float* gatesD = g_gates + (size_t)dir * M_ * G4H;
    volatile unsigned int* cnt = &g_cnt[dir][bg];

    for (int t = 0; t < L_; t++) {
        const int l  = dir ? (L_ - 1 - t) : t;
        const float* hread  = g_hbuf[dir][t & 1];
        float*       hwrite = g_hbuf[dir][(t & 1) ^ 1];

        // Wait for producer group covering this l
        {
            const unsigned need = (unsigned)(t >> 4) + 1u;
            while (*prod < need) { __nanosleep(20); }
        }

        // Prefetch input-projection preacts — in flight during h wait
        float gi[4];
#pragma unroll
        for (int bi = 0; bi < 4; bi++)
            gi[bi] = gatesD[(size_t)((b0 + bq * 4 + bi) * L_ + l) * G4H + grow_fin];

        // Wait for the 8 h-producers of this batch group (prev step)
        if (t > 0) {
            const unsigned int need = 8u * (unsigned)t;
            while (*cnt < need) { __nanosleep(20); }
        }

        // Stage previous h (8 batches x 256 units); L2-coherent loads
        const float4* hr4 = (const float4*)hread;
        for (int i = ctid; i < 8 * 64; i += 256) {
            int r = i >> 6, c4 = i & 63;
            hsm4[r * 65 + c4] = __ldcg(&hr4[(b0 + r) * 64 + c4]);
        }
        BAR_C();

        // 8x4 register-tiled GEMM, interleaved k-split (k4 = ks + 8*kk)
        float acc[32];
#pragma unroll
        for (int v = 0; v < 32; v++) acc[v] = 0.f;

#pragma unroll 2
        for (int kk = 0; kk < 8; kk++) {
            const int k4 = ks + kk * 8;
            float4 hv[4];
#pragma unroll
            for (int bi = 0; bi < 4; bi++)
                hv[bi] = hsm4[(bq * 4 + bi) * 65 + k4];
#pragma unroll
            for (int ri = 0; ri < 8; ri++) {
                float4 w = Wsm4[(rt * 8 + ri) * 65 + k4];
#pragma unroll
                for (int bi = 0; bi < 4; bi++) {
                    float a = acc[ri * 4 + bi];
                    a = fmaf(w.x, hv[bi].x, a);
                    a = fmaf(w.y, hv[bi].y, a);
                    a = fmaf(w.z, hv[bi].z, a);
                    a = fmaf(w.w, hv[bi].w, a);
                    acc[ri * 4 + bi] = a;
                }
            }
        }

        // K-split reduction: 3 butterfly rounds over lane bits 0..2 (ks)
#pragma unroll
        for (int s = 0; s < 3; s++) {
            const int half = 16 >> s;              // 16, 8, 4
            const bool up = (ks >> s) & 1;
#pragma unroll
            for (int i = 0; i < half; i++) {
                float send = up ? acc[i] : acc[i + half];
                float recv = __shfl_xor_sync(0xffffffffu, send, 1 << s);
                acc[i] = (up ? acc[i + half] : acc[i]) + recv;
            }
        }
#pragma unroll
        for (int bi = 0; bi < 4; bi++)
            Gsm[row_fin * 9 + bq * 4 + bi] = acc[bi] + gi[bi];
        BAR_C();

        // Gate nonlinearity + state update (PyTorch order i,f,g,o)
        float iv = Gsm[( 0 + ujj) * 9 + ub];
        float fv = Gsm[(32 + ujj) * 9 + ub];
        float gv = Gsm[(64 + ujj) * 9 + ub];
        float ov = Gsm[(96 + ujj) * 9 + ub];
        float si = __fdividef(1.f, 1.f + __expf(-iv));
        float sf = __fdividef(1.f, 1.f + __expf(-fv));
        float so = __fdividef(1.f, 1.f + __expf(-ov));
        c = sf * c + si * tanhf(gv);
        float h = so * tanhf(c);

        int bglob = b0 + ub;
        __stcg(&hwrite[bglob * H_ + j0 + ujj], h);
        __stcg(&g_hseq[(size_t)(bglob * L_ + l) * 512 + dir * H_ + j0 + ujj], h);

        // Publish: all h stores done -> bump group counter
        BAR_C();
        if (ctid == 0) {
            __threadfence();
            atomicAdd(&g_cnt[dir][bg], 1u);
        }
    }

    // =================== TAIL 1: logits slice ============================
    __threadfence();           // all my hseq stores visible
    BAR_C();
    if (ctid == 0) {           // wait both dirs of this bg complete
        volatile unsigned int* ca = &g_cnt[0][bg];
        volatile unsigned int* cb = &g_cnt[1][bg];
        while (*ca < 4096u) { __nanosleep(40); }
        while (*cb < 4096u) { __nanosleep(40); }
    }
    BAR_C();

    // Load W_out into freed producer-tile smem (prod==32 guaranteed: we
    // passed the t=496 producer wait, so producers are done with Ws/Es)
    float* Wo = sm + OFF_WS;           // 5632 floats
    float* bo = Wo + T_ * 512;         // 11 floats
    for (int i = ctid; i < T_ * 512; i += 256) Wo[i] = Wout[i];
    if (ctid < T_) bo[ctid] = bout[ctid];
    BAR_C();

    {
        const int s = dir * 8 + (sub & 7);           // slice 0..15
        const int bb = b0 + (ctid >> 5);
        const int ll = s * 32 + (ctid & 31);
        const int m  = bb * L_ + ll;
        const float4* h4 = (const float4*)(g_hseq + (size_t)m * 512);
        float acc[T_];
#pragma unroll
        for (int t = 0; t < T_; t++) acc[t] = 0.f;
        for (int k4 = 0; k4 < 128; k4++) {
            float4 h = h4[k4];
#pragma unroll
            for (int t = 0; t < T_; t++) {
                float4 w = *(const float4*)&Wo[t * 512 + k4 * 4];
                acc[t] = fmaf(h.x, w.x, fmaf(h.y, w.y, fmaf(h.z, w.z, fmaf(h.w, w.w, acc[t]))));
            }
        }
#pragma unroll
        for (int t = 0; t < T_; t++)
            g_logits[(size_t)m * T_ + t] = acc[t] + bo[t];
    }
    __threadfence();
    BAR_C();
    if (ctid == 0) atomicAdd(&g_lcnt[bg], 1u);

    // =================== TAIL 2: Viterbi (dir0 blocks, warp 0) ===========
    if (dir != 0) return;
    if (ctid >= 32) return;

    const int b = b0 + (sub & 7);       // this block decodes one batch
    const int j = ctid;

    if (j == 0) {
        volatile unsigned int* lc = &g_lcnt[bg];
        while (*lc < 16u) { __nanosleep(40); }
    }
    __syncwarp();

    float* lg = sm + OFF_W;                          // 5632 floats (reuse W_hh)
    unsigned char* bps = (unsigned char*)(sm + OFF_H); // 5621 bytes (reuse h)

    const float* src = g_logits + (size_t)b * L_ * T_;
    for (int i = j; i < L_ * T_; i += 32) lg[i] = __ldcg(&src[i]);

    const int jj = (j < T_) ? j : 0;
    float trC[T_];
#pragma unroll
    for (int i = 0; i < T_; i++) trC[i] = trans[i * T_ + jj];

    __syncwarp();
    float prev = (j < T_) ? lg[j] : -1e30f;

    for (int t = 1; t < L_; t++) {
        float lgt = lg[t * T_ + jj];
        float v[T_];
#pragma unroll
        for (int i = 0; i < T_; i++)
            v[i] = __shfl_sync(0xffffffffu, prev, i) + trC[i];

        // Value max via fmaxf tree (critical path); bp extracted off-path
        float m0 = fmaxf(v[0], v[1]), m1 = fmaxf(v[2], v[3]);
        float m2 = fmaxf(v[4], v[5]), m3 = fmaxf(v[6], v[7]);
        float m4 = fmaxf(v[8], v[9]);
        float n0 = fmaxf(m0, m1), n1 = fmaxf(m2, m3), n2 = fmaxf(m4, v[10]);
        float best = fmaxf(fmaxf(n0, n1), n2);
        prev = lgt + best;

        int bp = 10;
#pragma unroll
        for (int i = 9; i >= 0; i--) bp = (v[i] == best) ? i : bp;  // first index
        if (j < T_) bps[(t - 1) * T_ + j] = (unsigned char)bp;
    }

    // Final argmax over tags (first index wins); all lanes shuffle
    float fin[T_];
#pragma unroll
    for (int i = 0; i < T_; i++) fin[i] = __shfl_sync(0xffffffffu, prev, i);

    if (j == 0) {
        float best = fin[0]; int tag = 0;
#pragma unroll
        for (int i = 1; i < T_; i++)
            if (fin[i] > best) { best = fin[i]; tag = i; }
        if (scores) scores[b] = best;
        if (paths) {
            paths[b * L_ + (L_ - 1)] = (float)tag;
            int st = tag;
            for (int t = L_ - 2; t >= 0; t--) {
                st = bps[t * T_ + st];
                paths[b * L_ + t] = (float)st;
            }
        }
    }
}

// ---------------------------------------------------------------------------
// Launcher
// ---------------------------------------------------------------------------
extern "C" void kernel_launch(void* const* d_in, const int* in_sizes, int n_in,
                              void* d_out, int out_size)
{
    const int*   sent  = (const int*)  d_in[0];
    const float* emb   = (const float*)d_in[1];
    const float* Wih_f = (const float*)d_in[2];
    const float* Whh_f = (const float*)d_in[3];
    const float* b_f   = (const float*)d_in[4];
    const float* Wih_b = (const float*)d_in[5];
    const float* Whh_b = (const float*)d_in[6];
    const float* b_b   = (const float*)d_in[7];
    const float* Wout  = (const float*)d_in[8];
    const float* bout  = (const float*)d_in[9];
    const float* trans = (const float*)d_in[10];
    const float* h0    = (const float*)d_in[11];
    const float* c0    = (const float*)d_in[12];

    float* out = (float*)d_out;
    float* scores = nullptr;
    float* paths  = nullptr;
    if (out_size >= B_ + B_ * L_)      { scores = out; paths = out + B_; }
    else if (out_size == B_ * L_)      { paths = out; }
    else                               { scores = out; }

    // 1. init h buffers + counters
    init_kernel<<<128, 256>>>(h0);

    // 2. fully fused pipeline: producer GEMM + recurrence + logits + Viterbi
    const int smem_bytes = SMEM_FLOATS * (int)sizeof(float);
    cudaFuncSetAttribute(lstm_kernel, cudaFuncAttributeMaxDynamicSharedMemorySize, smem_bytes);
    lstm_kernel<<<NBLK_LSTM, 512, smem_bytes>>>(c0, Whh_f, Whh_b,
                                                sent, emb, Wih_f, b_f, Wih_b, b_b,
                                                Wout, bout, trans, scores, paths);
}

// round 13
// speedup vs baseline: 1.2126x; 1.2126x over previous
#include <cuda_runtime.h>
#include <math.h>

// Problem constants
#define B_   64
#define L_   512
#define D_   256
#define H_   256
#define T_   11
#define M_   (B_ * L_)      // 32768 rows (b*L + l)
#define G4H  (4 * H_)       // 1024 gate rows (i,f,g,o blocks of 256)

#define NBLK_LSTM 128       // persistent blocks (<=148 SMs, 1/SM)

// smem layout (floats)
#define OFF_W    0          // W_hh: 128 rows * 260
#define OFF_H    33280      // h: 8 * 260
#define OFF_G    35360      // G: 128 * 9
#define OFF_WS   36512      // producer W tiles: 2 * 16 * 132
#define OFF_ES   40736      // producer E tiles: 2 * 16 * 132
#define OFF_CNT  44960      // produced-group counter
#define SMEM_FLOATS 44964

#define BAR_C() asm volatile("bar.sync 1, 256;" ::: "memory")
#define BAR_P() asm volatile("bar.sync 2, 256;" ::: "memory")

// ---------------------------------------------------------------------------
// Scratch (static __device__ — no allocations allowed)
// ---------------------------------------------------------------------------
__device__ float g_gates[2 * 32768 * 1024];     // [dir][b*L+l][4H] input-proj + bias
__device__ float g_hseq[32768 * 512];           // [b*L+l][512] = concat(hf, hb)
__device__ float g_hbuf[2][2][B_ * H_];         // [dir][parity][b*H + j]
__device__ float g_logits[32768 * T_];          // [b*L+l][T]
__device__ unsigned int g_cnt[2][8];            // per-(dir, batch-group) h-completion

// ---------------------------------------------------------------------------
// Init: copy h0 into parity-0 h buffers, reset counters
// ---------------------------------------------------------------------------
__global__ void init_kernel(const float* __restrict__ h0) {
    int i = blockIdx.x * blockDim.x + threadIdx.x;
    if (i < 16) ((unsigned int*)g_cnt)[i] = 0u;
    if (i < 2 * B_ * H_) {
        int dir = i / (B_ * H_);
        int rem = i - dir * (B_ * H_);
        g_hbuf[dir][0][rem] = h0[i];
    }
}

// ---------------------------------------------------------------------------
// Fused persistent kernel: producer warps (0-7) compute the input projection
// for THIS block's private gate slice; compute warps (8-15) run the
// recurrence.  Producer->consumer sync is a block-local smem counter over
// 16-l groups.  Cross-block h exchange via global monotonic counters.
// (R11 version — proven; tail fusion reverted.)
// ---------------------------------------------------------------------------
__global__ __launch_bounds__(512, 1) void lstm_kernel(
    const float* __restrict__ c0,
    const float* __restrict__ Whh_f, const float* __restrict__ Whh_b,
    const int* __restrict__ sent, const float* __restrict__ emb,
    const float* __restrict__ Wih_f, const float* __restrict__ b_f,
    const float* __restrict__ Wih_b, const float* __restrict__ b_b)
{
    extern __shared__ float sm[];
    float4* Wsm4 = (float4*)(sm + OFF_W);          // 128 rows * 65 float4 (pad)
    float4* hsm4 = (float4*)(sm + OFF_H);          // 8 batches * 65 float4
    float*  Gsm  = sm + OFF_G;                     // 128 rows * 9 (pad)
    float*  Ws   = sm + OFF_WS;                    // [buf][k=16][n=128 pad 132]
    float*  Es   = sm + OFF_ES;                    // [buf][k=16][m=128 pad 132]
    volatile unsigned int* prod = (volatile unsigned int*)(sm + OFF_CNT);

    const int tid = threadIdx.x;
    const int bid = blockIdx.x;
    const int dir = bid >> 6;
    const int sub = bid & 63;
    const int bg  = sub >> 3;              // batch group 0..7
    const int b0  = bg * 8;                // batch tile base
    const int j0  = (sub & 7) * 32;        // hidden tile base

    if (tid == 0) *prod = 0u;

    // Compute threads preload W_hh slice: smem row r -> gate g=r>>5, j0+(r&31)
    if (tid >= 256) {
        const int ctid = tid - 256;
        const float4* Wg4 = (const float4*)(dir ? Whh_b : Whh_f);
        for (int idx = ctid; idx < 128 * 64; idx += 256) {
            int r = idx >> 6, k4 = idx & 63;
            int g = r >> 5, jj = r & 31;
            Wsm4[r * 65 + k4] = Wg4[(size_t)(g * H_ + j0 + jj) * 64 + k4];
        }
    }
    __syncthreads();   // everyone: prod init + W_hh visible

    if (tid < 256) {
        // ================= PRODUCER (warps 0-7, low priority) =============
        const float* Wih  = dir ? Wih_b : Wih_f;
        const float* bias = dir ? b_b  : b_f;
        float* outBase = g_gates + (size_t)dir * M_ * G4H;

        const int n   = tid & 127;          // stage row id (gate-row / m index)
        const int kq  = tid >> 7;           // 0/1: which 8-k half this thread stages
        const int nt  = tid >> 4;           // 0..15: n-tile (8 rows)
        const int mt  = tid & 15;           // 0..15: m-tile (8 cols)

        const int gblk = n >> 5, jj = n & 31;
        const float* wRow = Wih + (size_t)(gblk * H_ + j0 + jj) * D_ + kq * 8;

        const int growN0 = (nt >> 2) * H_ + j0 + (nt & 3) * 8;   // first of 8 n-rows
        float bias8[8];
#pragma unroll
        for (int j = 0; j < 8; j++) bias8[j] = bias[growN0 + j];

        for (int g = 0; g < 32; g++) {
            const int lbase = (dir ? (31 - g) : g) * 16;

            const int sv = sent[(b0 + (n & 7)) * L_ + lbase + (n >> 3)];
            const float* eRow = emb + (size_t)sv * D_ + kq * 8;

            // Preload chunk 0 into buf 0
            {
                float4 w0 = *(const float4*)(wRow);
                float4 w1 = *(const float4*)(wRow + 4);
                float4 e0 = *(const float4*)(eRow);
                float4 e1 = *(const float4*)(eRow + 4);
                float* Wd = Ws + (kq * 8) * 132 + n;
                Wd[0*132]=w0.x; Wd[1*132]=w0.y; Wd[2*132]=w0.z; Wd[3*132]=w0.w;
                Wd[4*132]=w1.x; Wd[5*132]=w1.y; Wd[6*132]=w1.z; Wd[7*132]=w1.w;
                float* Ed = Es + (kq * 8) * 132 + n;
                Ed[0*132]=e0.x; Ed[1*132]=e0.y; Ed[2*132]=e0.z; Ed[3*132]=e0.w;
                Ed[4*132]=e1.x; Ed[5*132]=e1.y; Ed[6*132]=e1.z; Ed[7*132]=e1.w;
            }
            BAR_P();

            float acc[8][8];
#pragma unroll
            for (int i = 0; i < 8; i++)
#pragma unroll
                for (int j = 0; j < 8; j++) acc[i][j] = 0.f;

            for (int c = 0; c < 16; c++) {
                float4 nw0, nw1, ne0, ne1;
                if (c < 15) {
                    nw0 = *(const float4*)(wRow + (c + 1) * 16);
                    nw1 = *(const float4*)(wRow + (c + 1) * 16 + 4);
                    ne0 = *(const float4*)(eRow + (c + 1) * 16);
                    ne1 = *(const float4*)(eRow + (c + 1) * 16 + 4);
                }
                const float* Wb = Ws + (c & 1) * 2112;
                const float* Eb = Es + (c & 1) * 2112;
#pragma unroll
                for (int k = 0; k < 16; k++) {
                    float4 a0 = *(const float4*)(Wb + k * 132 + nt * 8);
                    float4 a1 = *(const float4*)(Wb + k * 132 + nt * 8 + 4);
                    float4 bb0 = *(const float4*)(Eb + k * 132 + mt * 8);
                    float4 bb1 = *(const float4*)(Eb + k * 132 + mt * 8 + 4);
                    float wv[8] = {a0.x,a0.y,a0.z,a0.w,a1.x,a1.y,a1.z,a1.w};
                    float ev[8] = {bb0.x,bb0.y,bb0.z,bb0.w,bb1.x,bb1.y,bb1.z,bb1.w};
#pragma unroll
                    for (int i = 0; i < 8; i++)
#pragma unroll
                        for (int j = 0; j < 8; j++)
                            acc[i][j] = fmaf(wv[i], ev[j], acc[i][j]);
                }
                if (c < 15) {
                    float* Wd = Ws + ((c + 1) & 1) * 2112 + (kq * 8) * 132 + n;
                    Wd[0*132]=nw0.x; Wd[1*132]=nw0.y; Wd[2*132]=nw0.z; Wd[3*132]=nw0.w;
                    Wd[4*132]=nw1.x; Wd[5*132]=nw1.y; Wd[6*132]=nw1.z; Wd[7*132]=nw1.w;
                    float* Ed = Es + ((c + 1) & 1) * 2112 + (kq * 8) * 132 + n;
                    Ed[0*132]=ne0.x; Ed[1*132]=ne0.y; Ed[2*132]=ne0.z; Ed[3*132]=ne0.w;
                    Ed[4*132]=ne1.x; Ed[5*132]=ne1.y; Ed[6*132]=ne1.z; Ed[7*132]=ne1.w;
                }
                BAR_P();
            }

            // Write out 8 m columns (each 8 consecutive gate rows)
#pragma unroll
            for (int j = 0; j < 8; j++) {
                int m = mt * 8 + j;
                int bi = m & 7, li = m >> 3;
                float* dst = outBase +
                    ((size_t)(b0 + bi) * L_ + (lbase + li)) * G4H + growN0;
                float4 o0 = make_float4(acc[0][j] + bias8[0], acc[1][j] + bias8[1],
                                        acc[2][j] + bias8[2], acc[3][j] + bias8[3]);
                float4 o1 = make_float4(acc[4][j] + bias8[4], acc[5][j] + bias8[5],
                                        acc[6][j] + bias8[6], acc[7][j] + bias8[7]);
                __stcg((float4*)dst, o0);
                __stcg((float4*)(dst + 4), o1);
            }
            __threadfence();      // my gate stores visible before counter bump
            BAR_P();              // all producers done with this group
            if (tid == 0) *prod = (unsigned)(g + 1);
        }
        return;   // producers exit; compute warps continue alone
    }

    // ================= COMPUTE (warps 8-15, high priority) ================
    const int ctid = tid - 256;

    // Cell-update thread mapping
    const int ub = ctid >> 5, ujj = ctid & 31;
    float c = c0[dir * B_ * H_ + (b0 + ub) * H_ + j0 + ujj];

    // GEMM thread mapping: 8-way interleaved k-split
    const int ks   = ctid & 7;
    const int tile = ctid >> 3;
    const int rt   = tile >> 1;            // 0..15 -> rows rt*8..rt*8+7
    const int bq   = tile & 1;             // batches bq*4..bq*4+3
    const int ri_fin = ((ks & 1) << 2) | (ks & 2) | ((ks >> 2) & 1);
    const int row_fin = rt * 8 + ri_fin;
    const int grow_fin = (row_fin >> 5) * H_ + j0 + (row_fin & 31);

    const float* gatesD = g_gates + (size_t)dir * M_ * G4H;
    volatile unsigned int* cnt = &g_cnt[dir][bg];

    for (int t = 0; t < L_; t++) {
        const int l  = dir ? (L_ - 1 - t) : t;
        const float* hread  = g_hbuf[dir][t & 1];
        float*       hwrite = g_hbuf[dir][(t & 1) ^ 1];

        // Wait for producer group covering this l
        {
            const unsigned need = (unsigned)(t >> 4) + 1u;
            while (*prod < need) { __nanosleep(20); }
        }

        // Prefetch input-projection preacts — in flight during h wait
        float gi[4];
#pragma unroll
        for (int bi = 0; bi < 4; bi++)
            gi[bi] = gatesD[(size_t)((b0 + bq * 4 + bi) * L_ + l) * G4H + grow_fin];

        // Wait for the 8 h-producers of this batch group (prev step)
        if (t > 0) {
            const unsigned int need = 8u * (unsigned)t;
            while (*cnt < need) { __nanosleep(20); }
        }

        // Stage previous h (8 batches x 256 units); L2-coherent loads
        const float4* hr4 = (const float4*)hread;
        for (int i = ctid; i < 8 * 64; i += 256) {
            int r = i >> 6, c4 = i & 63;
            hsm4[r * 65 + c4] = __ldcg(&hr4[(b0 + r) * 64 + c4]);
        }
        BAR_C();

        // 8x4 register-tiled GEMM, interleaved k-split (k4 = ks + 8*kk)
        float acc[32];
#pragma unroll
        for (int v = 0; v < 32; v++) acc[v] = 0.f;

#pragma unroll 2
        for (int kk = 0; kk < 8; kk++) {
            const int k4 = ks + kk * 8;
            float4 hv[4];
#pragma unroll
            for (int bi = 0; bi < 4; bi++)
                hv[bi] = hsm4[(bq * 4 + bi) * 65 + k4];
#pragma unroll
            for (int ri = 0; ri < 8; ri++) {
                float4 w = Wsm4[(rt * 8 + ri) * 65 + k4];
#pragma unroll
                for (int bi = 0; bi < 4; bi++) {
                    float a = acc[ri * 4 + bi];
                    a = fmaf(w.x, hv[bi].x, a);
                    a = fmaf(w.y, hv[bi].y, a);
                    a = fmaf(w.z, hv[bi].z, a);
                    a = fmaf(w.w, hv[bi].w, a);
                    acc[ri * 4 + bi] = a;
                }
            }
        }

        // K-split reduction: 3 butterfly rounds over lane bits 0..2 (ks)
#pragma unroll
        for (int s = 0; s < 3; s++) {
            const int half = 16 >> s;              // 16, 8, 4
            const bool up = (ks >> s) & 1;
#pragma unroll
            for (int i = 0; i < half; i++) {
                float send = up ? acc[i] : acc[i + half];
                float recv = __shfl_xor_sync(0xffffffffu, send, 1 << s);
                acc[i] = (up ? acc[i + half] : acc[i]) + recv;
            }
        }
#pragma unroll
        for (int bi = 0; bi < 4; bi++)
            Gsm[row_fin * 9 + bq * 4 + bi] = acc[bi] + gi[bi];
        BAR_C();

        // Gate nonlinearity + state update (PyTorch order i,f,g,o)
        float iv = Gsm[( 0 + ujj) * 9 + ub];
        float fv = Gsm[(32 + ujj) * 9 + ub];
        float gv = Gsm[(64 + ujj) * 9 + ub];
        float ov = Gsm[(96 + ujj) * 9 + ub];
        float si = __fdividef(1.f, 1.f + __expf(-iv));
        float sf = __fdividef(1.f, 1.f + __expf(-fv));
        float so = __fdividef(1.f, 1.f + __expf(-ov));
        c = sf * c + si * tanhf(gv);
        float h = so * tanhf(c);

        int bglob = b0 + ub;
        __stcg(&hwrite[bglob * H_ + j0 + ujj], h);
        __stcg(&g_hseq[(size_t)(bglob * L_ + l) * 512 + dir * H_ + j0 + ujj], h);

        // Publish: all h stores done -> bump group counter
        BAR_C();
        if (ctid == 0) {
            __threadfence();
            atomicAdd(&g_cnt[dir][bg], 1u);
        }
    }
}

// ---------------------------------------------------------------------------
// Output projection: logits[m][t] = hseq[m] . W_out[t] + b_out[t]
// 256 blocks x 128 threads: full SM coverage, 2 CTAs/SM to overlap the
// W_out smem stage with compute.
// ---------------------------------------------------------------------------
__global__ __launch_bounds__(128) void logits_kernel(
    const float* __restrict__ Wout, const float* __restrict__ bout)
{
    __shared__ float Wo[T_ * 512];
    __shared__ float bo[T_];
    int tid = threadIdx.x;
    for (int i = tid; i < T_ * 512; i += 128) Wo[i] = Wout[i];
    if (tid < T_) bo[tid] = bout[tid];
    __syncthreads();

    int idx = blockIdx.x * 128 + tid;   // 0..32767
    const float4* h4 = (const float4*)(g_hseq + (size_t)idx * 512);
    float acc[T_];
#pragma unroll
    for (int t = 0; t < T_; t++) acc[t] = 0.f;

    for (int k4 = 0; k4 < 128; k4++) {
        float4 h = h4[k4];
#pragma unroll
        for (int t = 0; t < T_; t++) {
            float4 w = *(const float4*)&Wo[t * 512 + k4 * 4];
            acc[t] = fmaf(h.x, w.x, fmaf(h.y, w.y, fmaf(h.z, w.z, fmaf(h.w, w.w, acc[t]))));
        }
    }
#pragma unroll
    for (int t = 0; t < T_; t++)
        g_logits[(size_t)idx * T_ + t] = acc[t] + bo[t];
}

// ---------------------------------------------------------------------------
// Viterbi: one warp per batch.  Register/shuffle hot loop; value max via an
// fmaxf (FMNMX) tree on the critical path, backpointer extracted off-path by
// bit-exact first-index equality scan (best is exactly one of v[i], so this
// matches jnp.argmax first-index semantics exactly).
// ---------------------------------------------------------------------------
__global__ __launch_bounds__(32) void viterbi_kernel(
    const float* __restrict__ trans, float* scores, float* paths)
{
    __shared__ float lg[L_ * T_];                  // 22.5 KB
    __shared__ unsigned char bps[(L_ - 1) * T_];

    const int b = blockIdx.x;
    const int j = threadIdx.x;

    // Preload this batch's logits (coalesced across the warp)
    const float* src = g_logits + (size_t)b * L_ * T_;
    for (int i = j; i < L_ * T_; i += 32) lg[i] = src[i];

    // trans column into registers: trC[i] = trans[i][j]
    const int jj = (j < T_) ? j : 0;
    float trC[T_];
#pragma unroll
    for (int i = 0; i < T_; i++) trC[i] = trans[i * T_ + jj];

    __syncwarp();
    float prev = (j < T_) ? lg[j] : -1e30f;

    for (int t = 1; t < L_; t++) {
        float lgt = lg[t * T_ + jj];
        float v[T_];
#pragma unroll
        for (int i = 0; i < T_; i++)
            v[i] = __shfl_sync(0xffffffffu, prev, i) + trC[i];

        // Value max via fmaxf tree (critical path, FMNMX 4cyc each)
        float m0 = fmaxf(v[0], v[1]), m1 = fmaxf(v[2], v[3]);
        float m2 = fmaxf(v[4], v[5]), m3 = fmaxf(v[6], v[7]);
        float m4 = fmaxf(v[8], v[9]);
        float n0 = fmaxf(m0, m1), n1 = fmaxf(m2, m3), n2 = fmaxf(m4, v[10]);
        float best = fmaxf(fmaxf(n0, n1), n2);
        prev = lgt + best;                   // next-step dependency done here

        // Backpointer off the critical path: first i with v[i]==best
        int bp = 10;
#pragma unroll
        for (int i = 9; i >= 0; i--) bp = (v[i] == best) ? i : bp;
        if (j < T_) bps[(t - 1) * T_ + j] = (unsigned char)bp;
    }

    // Final argmax over tags (first index wins); all lanes shuffle
    float fin[T_];
#pragma unroll
    for (int i = 0; i < T_; i++) fin[i] = __shfl_sync(0xffffffffu, prev, i);

    if (j == 0) {
        float best = fin[0]; int tag = 0;
#pragma unroll
        for (int i = 1; i < T_; i++)
            if (fin[i] > best) { best = fin[i]; tag = i; }
        if (scores) scores[b] = best;
        if (paths) {
            paths[b * L_ + (L_ - 1)] = (float)tag;
            int st = tag;
            for (int t = L_ - 2; t >= 0; t--) {
                st = bps[t * T_ + st];
                paths[b * L_ + t] = (float)st;
            }
        }
    }
}

// ---------------------------------------------------------------------------
// Launcher
// ---------------------------------------------------------------------------
extern "C" void kernel_launch(void* const* d_in, const int* in_sizes, int n_in,
                              void* d_out, int out_size)
{
    const int*   sent  = (const int*)  d_in[0];
    const float* emb   = (const float*)d_in[1];
    const float* Wih_f = (const float*)d_in[2];
    const float* Whh_f = (const float*)d_in[3];
    const float* b_f   = (const float*)d_in[4];
    const float* Wih_b = (const float*)d_in[5];
    const float* Whh_b = (const float*)d_in[6];
    const float* b_b   = (const float*)d_in[7];
    const float* Wout  = (const float*)d_in[8];
    const float* bout  = (const float*)d_in[9];
    const float* trans = (const float*)d_in[10];
    const float* h0    = (const float*)d_in[11];
    const float* c0    = (const float*)d_in[12];

    float* out = (float*)d_out;
    float* scores = nullptr;
    float* paths  = nullptr;
    if (out_size >= B_ + B_ * L_)      { scores = out; paths = out + B_; }
    else if (out_size == B_ * L_)      { paths = out; }
    else                               { scores = out; }

    // 1. init h buffers + counters
    init_kernel<<<128, 256>>>(h0);

    // 2. fused producer + recurrence (128 co-resident blocks, ~176 KB smem)
    const int smem_bytes = SMEM_FLOATS * (int)sizeof(float);
    cudaFuncSetAttribute(lstm_kernel, cudaFuncAttributeMaxDynamicSharedMemorySize, smem_bytes);
    lstm_kernel<<<NBLK_LSTM, 512, smem_bytes>>>(c0, Whh_f, Whh_b,
                                                sent, emb, Wih_f, b_f, Wih_b, b_b);

    // 3. output projection (256 blocks x 128 threads)
    logits_kernel<<<M_ / 128, 128>>>(Wout, bout);

    // 4. Viterbi decode + write outputs
    viterbi_kernel<<<B_, 32>>>(trans, scores, paths);
}